// round 2
// baseline (speedup 1.0000x reference)
#include <cuda_runtime.h>
#include <cstdint>
#include <cstddef>

// ---------------------------------------------------------------------------
// SNN with cochlea front-end.  B=64, T=500, IN=256, HID=512, OUT=35.
//
// Pipeline (all sequential-state hoisted out of the big kernel):
//   1. prep_quant   : quantize + transpose weights (exact STE replication)
//   2. prep_rowsum  : row sums of quantized W2/W3/W4 (saturated-spike fast path)
//   3. cochlea_k    : per-(b,k) LIF recurrence -> packed spike masks [b][t][8]
//   4. list_k       : masks -> compacted active-k lists + counts
//   5. cur1_k       : exact layer-1 currents for ALL (b,t,n) via u8 SIMD sums
//   6. snn_main     : 128-thread CTA per batch elem; pure register LIF chain,
//                     3 barriers/step, prefetched cur1, rowsum fast path.
// ---------------------------------------------------------------------------

namespace {
constexpr int T_STEPS = 500;
constexpr int BATCH   = 64;
constexpr int N_IN    = 256;
constexpr int N_HID   = 512;
constexpr int N_OUT   = 35;
constexpr int BT      = BATCH * T_STEPS;
constexpr int TCHUNK  = 50;                    // t-steps per cur1_k block
constexpr float SCALEF = (float)((1.0 - 0.001) / 31.0);
constexpr size_t SPK_HID = (size_t)T_STEPS * BATCH * N_HID;
constexpr size_t SPK_OUT = (size_t)T_STEPS * BATCH * N_OUT;
}  // namespace

// Static device scratch (no runtime allocation).
__device__ unsigned char g_w1q[N_IN * N_HID];       // layer-1 levels [k][n] u8
__device__ float g_q2T[N_HID * N_HID];              // quantized W2^T [k][n]
__device__ float g_q3T[N_HID * N_HID];              // quantized W3^T [k][n]
__device__ float g_q4T[N_HID * N_OUT];              // quantized W4^T [k][o]
__device__ float g_rs2[N_HID];
__device__ float g_rs3[N_HID];
__device__ float g_rs4[N_OUT];
__device__ unsigned g_chmask[BT * 8];               // cochlea spike masks
__device__ unsigned char g_chlist[(size_t)BT * 256];// compacted active-k lists
__device__ int g_chcnt[BT];                         // active counts
__device__ float g_cur1[(size_t)BT * N_HID];        // precomputed layer-1 currents

// Exact replication of reference fake_quant (fp32, round-half-even, no FMA).
__device__ __forceinline__ float quantw(float w) {
    float wc = fminf(fmaxf(w, 0.001f), 1.0f);
    float l  = rintf((wc - 0.001f) / SCALEF);
    return __fadd_rn(__fmul_rn(l, SCALEF), 0.001f);
}

// ---------------------------------------------------------------------------
__global__ void prep_quant(const float* __restrict__ W1, const float* __restrict__ W2,
                           const float* __restrict__ W3, const float* __restrict__ W4) {
    int idx = blockIdx.x * blockDim.x + threadIdx.x;
    if (idx < N_HID * N_IN) {
        int n = idx / N_IN, k = idx % N_IN;
        float wc = fminf(fmaxf(W1[idx], 0.001f), 1.0f);
        float l  = rintf((wc - 0.001f) / SCALEF);
        g_w1q[k * N_HID + n] = (unsigned char)(int)l;
    }
    if (idx < N_HID * N_HID) {
        int n = idx / N_HID, k = idx % N_HID;
        g_q2T[k * N_HID + n] = quantw(W2[idx]);
        g_q3T[k * N_HID + n] = quantw(W3[idx]);
    }
    if (idx < N_OUT * N_HID) {
        int o = idx / N_HID, k = idx % N_HID;
        g_q4T[k * N_OUT + o] = quantw(W4[idx]);
    }
}

__global__ void prep_rowsum() {
    int n = blockIdx.x * blockDim.x + threadIdx.x;
    if (n < N_HID) {
        float s2 = 0.f, s3 = 0.f;
        for (int k = 0; k < N_HID; ++k) {
            s2 = __fadd_rn(s2, g_q2T[k * N_HID + n]);
            s3 = __fadd_rn(s3, g_q3T[k * N_HID + n]);
        }
        g_rs2[n] = s2;
        g_rs3[n] = s3;
        if (n < N_OUT) {
            float s4 = 0.f;
            for (int k = 0; k < N_HID; ++k) s4 = __fadd_rn(s4, g_q4T[k * N_OUT + n]);
            g_rs4[n] = s4;
        }
    }
}

// ---------------------------------------------------------------------------
// Cochlea: 64 blocks x 256 threads; one thread = one (b,k) recurrence.
// x row staged in SMEM; processed 4 steps at a time from float4 reads.
// ---------------------------------------------------------------------------
__global__ void __launch_bounds__(256, 1) cochlea_k(
    const float* __restrict__ x, const float* __restrict__ Wch,
    const float* __restrict__ cb)
{
    __shared__ float xs[T_STEPS];
    const int b = blockIdx.x, k = threadIdx.x;
    const int lane = k & 31, warp = k >> 5;
    for (int i = k; i < T_STEPS; i += 256) xs[i] = x[(size_t)b * T_STEPS + i];
    const float wch = Wch[k];
    const float bch = fminf(fmaxf(cb[k], 0.f), 1.f);
    float chm = 0.f;
    __syncthreads();
    const float4* x4 = (const float4*)xs;
    for (int t4 = 0; t4 < T_STEPS / 4; ++t4) {
        float4 xv = x4[t4];
        #pragma unroll
        for (int j = 0; j < 4; ++j) {
            float xt = (j == 0) ? xv.x : (j == 1) ? xv.y : (j == 2) ? xv.z : xv.w;
            float cur = __fmul_rn(xt, wch);
            float rst = (chm > 1.f) ? 1.f : 0.f;
            chm = __fadd_rn(__fadd_rn(__fmul_rn(bch, chm), cur), -rst);
            unsigned bal = __ballot_sync(0xffffffffu, chm > 1.f);
            if (lane == 0) g_chmask[((size_t)b * T_STEPS + t4 * 4 + j) * 8 + warp] = bal;
        }
    }
}

// ---------------------------------------------------------------------------
// Compaction: one warp per (b,t) -> list of active k (u8) + count.
// ---------------------------------------------------------------------------
__global__ void __launch_bounds__(256, 4) list_k() {
    int wid  = blockIdx.x * 8 + (threadIdx.x >> 5);   // 4000 blocks * 8 warps = BT
    int lane = threadIdx.x & 31;
    unsigned m = (lane < 8) ? g_chmask[(size_t)wid * 8 + lane] : 0u;
    int c = __popc(m);
    int off = 0, tot = 0;
    #pragma unroll
    for (int j = 0; j < 8; ++j) {
        int cj = __shfl_sync(0xffffffffu, c, j);
        if (j < lane) off += cj;
        tot += cj;
    }
    unsigned char* dst = g_chlist + (size_t)wid * 256;
    while (m) {
        int bb = __ffs(m) - 1; m &= m - 1;
        dst[off++] = (unsigned char)(lane * 32 + bb);
    }
    if (lane == 0) g_chcnt[wid] = tot;
}

// ---------------------------------------------------------------------------
// cur1 precompute: block = (b, t-chunk of 50).  512 threads = 4 groups x 128.
// Group g computes step t0+g, t0+g+4, ...  Thread 'sub' owns neurons 4sub..4sub+3
// via u32 SIMD byte accumulation (levels<=31, groups of 8 => no byte carry).
// Exact integer arithmetic -> bitwise-stable currents.
// ---------------------------------------------------------------------------
__global__ void __launch_bounds__(512, 1) cur1_k() {
    extern __shared__ unsigned char sm[];
    unsigned* sw = (unsigned*)sm;                         // 128 KB weights [k][n/4]
    unsigned char* slist = sm + N_IN * N_HID;             // TCHUNK*256 lists
    const int b = blockIdx.x, t0 = blockIdx.y * TCHUNK;
    const int tid = threadIdx.x;

    {   // stage weights
        const uint4* src = (const uint4*)g_w1q;
        uint4* dst = (uint4*)sm;
        for (int i = tid; i < (N_IN * N_HID) / 16; i += 512) dst[i] = src[i];
    }
    {   // stage lists for this chunk
        const uint4* src = (const uint4*)(g_chlist + ((size_t)b * T_STEPS + t0) * 256);
        uint4* dst = (uint4*)slist;
        for (int i = tid; i < (TCHUNK * 256) / 16; i += 512) dst[i] = src[i];
    }
    __syncthreads();

    const int g = tid >> 7, sub = tid & 127;
    for (int tt = t0 + g; tt < t0 + TCHUNK; tt += 4) {
        const int cc = g_chcnt[b * T_STEPS + tt];
        const unsigned char* lst = slist + (tt - t0) * 256;
        int a0 = 0, a1 = 0, a2 = 0, a3 = 0;
        int j = 0;
        while (j < cc) {
            int je = min(j + 8, cc);
            unsigned v = 0;
            for (; j < je; ++j) {
                int k = lst[j];
                v += sw[k * 128 + sub];      // 4 neurons' levels, SIMD add (no carry)
            }
            a0 += v & 255; a1 += (v >> 8) & 255; a2 += (v >> 16) & 255; a3 += v >> 24;
        }
        const float base = __fmul_rn(0.001f, (float)cc);
        float4 o;
        o.x = __fadd_rn(base, __fmul_rn(SCALEF, (float)a0));
        o.y = __fadd_rn(base, __fmul_rn(SCALEF, (float)a1));
        o.z = __fadd_rn(base, __fmul_rn(SCALEF, (float)a2));
        o.w = __fadd_rn(base, __fmul_rn(SCALEF, (float)a3));
        ((float4*)(g_cur1 + ((size_t)b * T_STEPS + tt) * N_HID))[sub] = o;
    }
}

// ---------------------------------------------------------------------------
// Rare-path correction: build 512-bit zero mask in SMEM from per-thread nibbles,
// then subtract q^T columns of zero-spiking neurons.  total==512 => exact 0.
// ---------------------------------------------------------------------------
__device__ __forceinline__ float4 correct_hid(unsigned* zmask, float4 rs, int nib,
                                              const float* __restrict__ qT, int tid) {
    if (tid < 16) zmask[tid] = 0u;
    __syncthreads();
    if (nib) atomicOr(&zmask[tid >> 3], ((unsigned)nib) << ((tid & 7) * 4));
    __syncthreads();
    int total = 0;
    float4 c = rs;
    for (int w = 0; w < 16; ++w) {
        unsigned m = zmask[w];
        total += __popc(m);
        while (m) {
            int bb = __ffs(m) - 1; m &= m - 1;
            int k = w * 32 + bb;
            float4 q = __ldg((const float4*)(qT + (size_t)k * N_HID) + tid);
            c.x = __fadd_rn(c.x, -q.x);
            c.y = __fadd_rn(c.y, -q.y);
            c.z = __fadd_rn(c.z, -q.z);
            c.w = __fadd_rn(c.w, -q.w);
        }
    }
    if (total == N_HID) c = make_float4(0.f, 0.f, 0.f, 0.f);
    __syncthreads();   // protect zmask from next build
    return c;
}

// ---------------------------------------------------------------------------
// Main recurrence: 64 CTAs x 128 threads; thread t owns neurons 4t..4t+3.
// ---------------------------------------------------------------------------
__global__ void __launch_bounds__(128, 1) snn_main(
    const float* __restrict__ pb1, const float* __restrict__ pb2,
    const float* __restrict__ pb3, const float* __restrict__ pb4,
    float* __restrict__ out)
{
    __shared__ unsigned s_zmask[16];
    const int b = blockIdx.x, tid = threadIdx.x;

    const float beta1 = fminf(fmaxf(pb1[0], 0.f), 1.f);
    const float beta2 = fminf(fmaxf(pb2[0], 0.f), 1.f);
    const float beta3 = fminf(fmaxf(pb3[0], 0.f), 1.f);
    const float beta4 = fminf(fmaxf(pb4[0], 0.f), 1.f);

    const float4 rs2v = ((const float4*)g_rs2)[tid];
    const float4 rs3v = ((const float4*)g_rs3)[tid];
    const float  rs4v = (tid < N_OUT) ? g_rs4[tid] : 0.f;

    float4 m1 = make_float4(0,0,0,0), m2 = m1, m3 = m1;
    float  m4 = 0.f;

    const float* curb = g_cur1 + (size_t)b * T_STEPS * N_HID;
    float4 nxt0 = __ldg((const float4*)curb + tid);
    float4 nxt1 = __ldg((const float4*)(curb + N_HID) + tid);

    float* o1 = out + (size_t)b * N_HID + 4 * tid;
    float* o2 = o1 + SPK_HID;
    float* o3 = o2 + SPK_HID;
    float* o4 = out + 3 * SPK_HID + (size_t)b * N_OUT + tid;
    float* om = o4 + SPK_OUT;

    for (int t = 0; t < T_STEPS; ++t) {
        float4 c1 = nxt0;
        nxt0 = nxt1;
        if (t + 2 < T_STEPS)
            nxt1 = __ldg((const float4*)(curb + (size_t)(t + 2) * N_HID) + tid);

        // ---- layer 1 ----
        float r;
        r = (m1.x > 1.f) ? 1.f : 0.f; m1.x = __fadd_rn(__fadd_rn(__fmul_rn(beta1, m1.x), c1.x), -r);
        r = (m1.y > 1.f) ? 1.f : 0.f; m1.y = __fadd_rn(__fadd_rn(__fmul_rn(beta1, m1.y), c1.y), -r);
        r = (m1.z > 1.f) ? 1.f : 0.f; m1.z = __fadd_rn(__fadd_rn(__fmul_rn(beta1, m1.z), c1.z), -r);
        r = (m1.w > 1.f) ? 1.f : 0.f; m1.w = __fadd_rn(__fadd_rn(__fmul_rn(beta1, m1.w), c1.w), -r);
        bool sx = m1.x > 1.f, sy = m1.y > 1.f, sz = m1.z > 1.f, sw = m1.w > 1.f;
        ((float4*)(o1 + (size_t)t * (BATCH * N_HID)))[0] =
            make_float4(sx ? 1.f : 0.f, sy ? 1.f : 0.f, sz ? 1.f : 0.f, sw ? 1.f : 0.f);
        int nib = (!sx) | ((int)(!sy) << 1) | ((int)(!sz) << 2) | ((int)(!sw) << 3);
        int cnt = __syncthreads_count(nib != 0);
        float4 c2 = (cnt == 0) ? rs2v : correct_hid(s_zmask, rs2v, nib, g_q2T, tid);

        // ---- layer 2 ----
        r = (m2.x > 1.f) ? 1.f : 0.f; m2.x = __fadd_rn(__fadd_rn(__fmul_rn(beta2, m2.x), c2.x), -r);
        r = (m2.y > 1.f) ? 1.f : 0.f; m2.y = __fadd_rn(__fadd_rn(__fmul_rn(beta2, m2.y), c2.y), -r);
        r = (m2.z > 1.f) ? 1.f : 0.f; m2.z = __fadd_rn(__fadd_rn(__fmul_rn(beta2, m2.z), c2.z), -r);
        r = (m2.w > 1.f) ? 1.f : 0.f; m2.w = __fadd_rn(__fadd_rn(__fmul_rn(beta2, m2.w), c2.w), -r);
        sx = m2.x > 1.f; sy = m2.y > 1.f; sz = m2.z > 1.f; sw = m2.w > 1.f;
        ((float4*)(o2 + (size_t)t * (BATCH * N_HID)))[0] =
            make_float4(sx ? 1.f : 0.f, sy ? 1.f : 0.f, sz ? 1.f : 0.f, sw ? 1.f : 0.f);
        nib = (!sx) | ((int)(!sy) << 1) | ((int)(!sz) << 2) | ((int)(!sw) << 3);
        cnt = __syncthreads_count(nib != 0);
        float4 c3 = (cnt == 0) ? rs3v : correct_hid(s_zmask, rs3v, nib, g_q3T, tid);

        // ---- layer 3 ----
        r = (m3.x > 1.f) ? 1.f : 0.f; m3.x = __fadd_rn(__fadd_rn(__fmul_rn(beta3, m3.x), c3.x), -r);
        r = (m3.y > 1.f) ? 1.f : 0.f; m3.y = __fadd_rn(__fadd_rn(__fmul_rn(beta3, m3.y), c3.y), -r);
        r = (m3.z > 1.f) ? 1.f : 0.f; m3.z = __fadd_rn(__fadd_rn(__fmul_rn(beta3, m3.z), c3.z), -r);
        r = (m3.w > 1.f) ? 1.f : 0.f; m3.w = __fadd_rn(__fadd_rn(__fmul_rn(beta3, m3.w), c3.w), -r);
        sx = m3.x > 1.f; sy = m3.y > 1.f; sz = m3.z > 1.f; sw = m3.w > 1.f;
        ((float4*)(o3 + (size_t)t * (BATCH * N_HID)))[0] =
            make_float4(sx ? 1.f : 0.f, sy ? 1.f : 0.f, sz ? 1.f : 0.f, sw ? 1.f : 0.f);
        nib = (!sx) | ((int)(!sy) << 1) | ((int)(!sz) << 2) | ((int)(!sw) << 3);
        cnt = __syncthreads_count(nib != 0);

        // ---- layer 4 (scalar, threads 0..34) ----
        float c4 = rs4v;
        if (cnt != 0) {
            if (tid < 16) s_zmask[tid] = 0u;
            __syncthreads();
            if (nib) atomicOr(&s_zmask[tid >> 3], ((unsigned)nib) << ((tid & 7) * 4));
            __syncthreads();
            int total = 0;
            float acc = rs4v;
            for (int w = 0; w < 16; ++w) {
                unsigned m = s_zmask[w];
                total += __popc(m);
                if (tid < N_OUT) {
                    while (m) {
                        int bb = __ffs(m) - 1; m &= m - 1;
                        acc = __fadd_rn(acc, -__ldg(g_q4T + (size_t)(w * 32 + bb) * N_OUT + tid));
                    }
                }
            }
            c4 = (total == N_HID) ? 0.f : acc;
            __syncthreads();
        }
        if (tid < N_OUT) {
            r = (m4 > 1.f) ? 1.f : 0.f;
            m4 = __fadd_rn(__fadd_rn(__fmul_rn(beta4, m4), c4), -r);
            o4[(size_t)t * (BATCH * N_OUT)] = (m4 > 1.f) ? 1.f : 0.f;
            om[(size_t)t * (BATCH * N_OUT)] = m4;
        }
    }
}

// ---------------------------------------------------------------------------
extern "C" void kernel_launch(void* const* d_in, const int* in_sizes, int n_in,
                              void* d_out, int out_size) {
    const float* x   = (const float*)d_in[0];
    const float* Wch = (const float*)d_in[1];
    const float* W1  = (const float*)d_in[2];
    const float* W2  = (const float*)d_in[3];
    const float* W3  = (const float*)d_in[4];
    const float* W4  = (const float*)d_in[5];
    const float* cb  = (const float*)d_in[6];
    const float* b1  = (const float*)d_in[7];
    const float* b2  = (const float*)d_in[8];
    const float* b3  = (const float*)d_in[9];
    const float* b4  = (const float*)d_in[10];
    float* out = (float*)d_out;

    const int cur1_smem = N_IN * N_HID + TCHUNK * 256;   // 128KB + 12.8KB
    cudaFuncSetAttribute(cur1_k, cudaFuncAttributeMaxDynamicSharedMemorySize, cur1_smem);

    prep_quant<<<1024, 256>>>(W1, W2, W3, W4);
    prep_rowsum<<<2, 256>>>();
    cochlea_k<<<BATCH, 256>>>(x, Wch, cb);
    list_k<<<BT / 8, 256>>>();
    cur1_k<<<dim3(BATCH, T_STEPS / TCHUNK), 512, cur1_smem>>>();
    snn_main<<<BATCH, 128>>>(b1, b2, b3, b4, out);
}